// round 14
// baseline (speedup 1.0000x reference)
#include <cuda_runtime.h>
#include <cuda_bf16.h>
#include <cstdint>

#define N_NODES 207
#define N_EDGES 1722
#define N_SLOTS 288
#define LDIM    64
#define BATCH   1024
#define ADJ_CAP 3456            // 2*N_EDGES = 3444, padded
#define MT      13              // m16 tiles (208 rows)
#define KT      13              // k16 tiles (208 cols)

// ---------------- device-global scratch (no allocs allowed) ----------------
__device__ int g_ndeg[N_NODES];
__device__ int g_nodebeg[N_NODES];
__device__ __align__(16) unsigned short g_adj_nbr[ADJ_CAP];   // neighbor node id
__device__ __align__(16) unsigned short g_adj_edge[ADJ_CAP];  // edge idx
// dense -A in mma.sync A-FRAGMENT order: [slot][mtile*13+ktile][lane] = {a0,a1,a2,a3}
__device__ __align__(16) uint4 g_lapfrag[N_SLOTS][MT * KT][32];  // 24.9 MB
__device__ float g_sc[N_SLOTS][208];                             // deg + 1 + wsl

__device__ __forceinline__ uint32_t smem_u32(const void* p) {
    uint32_t a;
    asm("{ .reg .u64 t; cvta.to.shared.u64 t, %1; cvt.u32.u64 %0, t; }"
        : "=r"(a) : "l"(p));
    return a;
}
__device__ __forceinline__ unsigned pk_bf2(float lo, float hi) {
    __nv_bfloat162 h = __floats2bfloat162_rn(lo, hi);
    return *reinterpret_cast<unsigned*>(&h);
}

// ---------------- setup 1: deterministic CSR (single block, proven) --------
__global__ __launch_bounds__(1024, 1)
void build_csr_kernel(const int* __restrict__ edge_i,
                      const int* __restrict__ edge_j) {
    __shared__ int s_ei[N_EDGES];
    __shared__ int s_ej[N_EDGES];
    __shared__ int s_off[N_NODES + 1];
    __shared__ int s_wcnt[32][208];
    const int tid  = threadIdx.x;
    const int warp = tid >> 5;
    const int lane = tid & 31;

    for (int i = tid; i < N_EDGES; i += 1024) {
        s_ei[i] = edge_i[i];
        s_ej[i] = edge_j[i];
    }
    for (int v = tid; v < N_NODES + 1; v += 1024) s_off[v] = 0;
    for (int i = tid; i < 32 * 208; i += 1024) ((int*)s_wcnt)[i] = 0;
    __syncthreads();

    for (int idx = tid; idx < 2 * N_EDGES; idx += 1024) {
        const int e = idx >> 1;
        atomicAdd(&s_off[(idx & 1) ? s_ej[e] : s_ei[e]], 1);
    }
    __syncthreads();

    if (tid < N_NODES) g_ndeg[tid] = s_off[tid];
    __syncthreads();

    if (tid == 0) {                       // serial scan (207 iters, cheap)
        int run = 0;
        for (int v = 0; v < N_NODES; v++) {
            const int c = s_off[v];
            s_off[v] = run;
            run += c;
        }
        s_off[N_NODES] = run;
    }
    __syncthreads();
    if (tid < N_NODES) g_nodebeg[tid] = s_off[tid];

    // single-chunk deterministic scatter: 4 rounds per lane
    int myrank[4], myv[4], mynbr[4], mye[4];
    #pragma unroll
    for (int r = 0; r < 4; ++r) {
        const int idx = tid * 4 + r;
        const bool valid = idx < 2 * N_EDGES;
        int v = 207, nbr = 0, e = 0;
        if (valid) {
            e = idx >> 1;
            if (idx & 1) { v = s_ej[e]; nbr = s_ei[e]; }
            else         { v = s_ei[e]; nbr = s_ej[e]; }
        }
        const int prefix = s_wcnt[warp][v];
        const unsigned mask = __match_any_sync(0xffffffffu, v);
        const int rin = __popc(mask & ((1u << lane) - 1u));
        myv[r] = v; mynbr[r] = nbr; mye[r] = e;
        myrank[r] = prefix + rin;
        __syncwarp();
        if (lane == (__ffs(mask) - 1)) s_wcnt[warp][v] = prefix + __popc(mask);
        __syncwarp();
    }
    __syncthreads();

    if (tid < 208) {
        int run = (tid < N_NODES) ? s_off[tid] : 0;
        #pragma unroll
        for (int w2 = 0; w2 < 32; ++w2) {
            const int t = s_wcnt[w2][tid];
            s_wcnt[w2][tid] = run;
            run += t;
        }
    }
    __syncthreads();

    #pragma unroll
    for (int r = 0; r < 4; ++r) {
        const int idx = tid * 4 + r;
        if (idx < 2 * N_EDGES) {
            const int pos = s_wcnt[warp][myv[r]] + myrank[r];
            g_adj_nbr[pos]  = (unsigned short)mynbr[r];
            g_adj_edge[pos] = (unsigned short)mye[r];
        }
    }
}

// ---------------- setup 2: dense -A strips -> fragment-ordered tiles -------
__global__ __launch_bounds__(128, 4)
void lap_build_kernel(const float* __restrict__ weight_diff,   // (S,E)
                      const float* __restrict__ weight_sl) {   // (S,N)
    __shared__ float s_w[1728];
    __shared__ float strip[16][208];
    const int s   = blockIdx.x / MT;
    const int mt  = blockIdx.x - s * MT;
    const int tid = threadIdx.x;
    const float* wrow = weight_diff + (size_t)s * N_EDGES;

    for (int i = tid; i < 1728; i += 128)
        s_w[i] = (i < N_EDGES) ? wrow[i] : 0.0f;
    for (int i = tid; i < 16 * 208; i += 128)
        ((float*)strip)[i] = 0.0f;
    __syncthreads();

    if (tid < 16) {
        const int w = mt * 16 + tid;
        if (w < N_NODES) {
            const int beg = g_nodebeg[w];
            const int dn  = g_ndeg[w];
            float deg = 0.0f;
            for (int i = 0; i < dn; ++i) {          // deterministic CSR order
                const int u = (int)g_adj_nbr[beg + i];
                const float we = s_w[(int)g_adj_edge[beg + i]];
                deg += we;
                strip[tid][u] -= we;
            }
            g_sc[s][w] = deg + 1.0f + weight_sl[(size_t)s * N_NODES + w];
        }
    }
    __syncthreads();

    // emit fragments: warp wp handles ktiles wp, wp+4, ...
    const int wp   = tid >> 5;
    const int lane = tid & 31;
    const int r    = lane >> 2;
    for (int kt = wp; kt < KT; kt += 4) {
        const int cb = (lane & 3) * 2 + kt * 16;
        uint4 f;
        f.x = pk_bf2(strip[r][cb],         strip[r][cb + 1]);
        f.y = pk_bf2(strip[r + 8][cb],     strip[r + 8][cb + 1]);
        f.z = pk_bf2(strip[r][cb + 8],     strip[r][cb + 9]);
        f.w = pk_bf2(strip[r + 8][cb + 8], strip[r + 8][cb + 9]);
        g_lapfrag[s][mt * KT + kt][lane] = f;
    }
}

// ---------------- main: HMMA GEMM, one CTA (416 thr = 13 warps) per batch --
// smem: bf16 x tile (pitch 33 u32) @0 [27456 B], B = x^T bf16 [n=64][k=208,
// pitch 216 hw = 432 B] @27520 [27648 B]. Warp = one m16 strip, ALL active.
// Per k-step: prefetched LDG.128 (A frag) + 4x(ldmatrix.x4 + 2 mma.sync).
// 416 thr @ occ 2 -> 78-reg budget: 32 fp32 accs live in registers, no spill.
#define XT_W      33
#define SB_OFF    27520
#define PB_B      432
#define MAIN_SMEM (27520 + 27648)
#define NTHREADS  416

__global__ __launch_bounds__(NTHREADS, 2)
void gemm_main_kernel(const float* __restrict__ inputs,      // (B,2,N,L)
                      const float* __restrict__ bias_diff,   // (S,N)
                      const int*   __restrict__ ind,         // (B,)
                      float*       __restrict__ out)         // (B,N,L)
{
    extern __shared__ __align__(16) char smem[];
    uint32_t* xt = (uint32_t*)smem;
    const int b    = blockIdx.x;
    const int tid  = threadIdx.x;
    const int warp = tid >> 5;           // 0..12, all run the GEMM
    const int lane = tid & 31;
    const int slot = ind[b];
    const float* __restrict__ xg = inputs + (size_t)b * 2 * N_NODES * LDIM;

    // ---- stage 1: x -> bf16 tile (row-major, pitch 33 u32) ----------------
    {
        const float4* src = (const float4*)xg;
        #pragma unroll 4
        for (int i = tid; i < 3312; i += NTHREADS) {   // 207*16 float4
            const float4 v = src[i];
            const int k = i >> 4, j = i & 15;
            xt[XT_W * k + 2 * j]     = pk_bf2(v.x, v.y);
            xt[XT_W * k + 2 * j + 1] = pk_bf2(v.z, v.w);
        }
    }
    if (tid < XT_W) xt[XT_W * 207 + tid] = 0;          // zero pad row 207
    __syncthreads();

    // ---- stage 2: transpose -> B [n][k-pair] u32, pitch 108 u32 -----------
    {
        const unsigned short* x16 = (const unsigned short*)xt;   // pitch 66 hw
        uint32_t* B32 = (uint32_t*)(smem + SB_OFF);
        for (int i = tid; i < 64 * 104; i += NTHREADS) {
            const int n = i / 104;
            const int kp = i - n * 104;
            const int k = kp * 2;
            const unsigned h0 = x16[k * 66 + n];
            const unsigned h1 = x16[(k + 1) * 66 + n];
            B32[n * 108 + kp] = h0 | (h1 << 16);
        }
    }
    __syncthreads();

    {
        // per-lane ldmatrix base: matrix mi = lane>>3; row-within = lane&7
        const uint32_t sB = smem_u32(smem + SB_OFF);
        const int mi = lane >> 3;
        const uint32_t ldsm_base = sB
            + (uint32_t)((lane & 7) + (mi >> 1) * 8) * PB_B   // n row
            + (uint32_t)(mi & 1) * 16;                        // k-half

        const uint4* afrag = &g_lapfrag[slot][warp * KT][0] + lane;

        float acc[32];
        #pragma unroll
        for (int i = 0; i < 32; ++i) acc[i] = 0.0f;

        uint4 a = __ldg(afrag);                      // k-step 0 prefetched

        #pragma unroll 1
        for (int kt = 0; kt < KT; ++kt) {
            const uint4 an = (kt < KT - 1) ? __ldg(afrag + (kt + 1) * 32) : a;
            const uint32_t kb = ldsm_base + (uint32_t)kt * 32;
            #pragma unroll
            for (int np = 0; np < 4; ++np) {
                uint32_t b0, b1, b2, b3;
                asm volatile(
                    "ldmatrix.sync.aligned.m8n8.x4.shared.b16 {%0,%1,%2,%3}, [%4];"
                    : "=r"(b0), "=r"(b1), "=r"(b2), "=r"(b3)
                    : "r"(kb + (uint32_t)np * (16u * PB_B)));
                float* c = acc + np * 8;
                asm volatile(
                    "mma.sync.aligned.m16n8k16.row.col.f32.bf16.bf16.f32 "
                    "{%0,%1,%2,%3}, {%4,%5,%6,%7}, {%8,%9}, {%0,%1,%2,%3};"
                    : "+f"(c[0]), "+f"(c[1]), "+f"(c[2]), "+f"(c[3])
                    : "r"(a.x), "r"(a.y), "r"(a.z), "r"(a.w), "r"(b0), "r"(b1));
                asm volatile(
                    "mma.sync.aligned.m16n8k16.row.col.f32.bf16.bf16.f32 "
                    "{%0,%1,%2,%3}, {%4,%5,%6,%7}, {%8,%9}, {%0,%1,%2,%3};"
                    : "+f"(c[4]), "+f"(c[5]), "+f"(c[6]), "+f"(c[7])
                    : "r"(a.x), "r"(a.y), "r"(a.z), "r"(a.w), "r"(b2), "r"(b3));
            }
            a = an;
        }

        // ---- epilogue: D + sc*x + bias (fp32, x from global L2) -----------
        const int w0 = warp * 16 + (lane >> 2);       // always < 207
        const int w1 = w0 + 8;
        const int cb = (lane & 3) * 2;
        const float sc0 = g_sc[slot][w0];
        const float bi0 = __ldg(bias_diff + (size_t)slot * N_NODES + w0);
        const bool  v1  = (w1 < N_NODES);
        const float sc1 = v1 ? g_sc[slot][w1] : 0.0f;
        const float bi1 = v1 ? __ldg(bias_diff + (size_t)slot * N_NODES + w1) : 0.0f;
        const float* x0 = xg + w0 * LDIM;
        const float* x1 = xg + (v1 ? w1 : w0) * LDIM;
        float* o0 = out + ((size_t)b * N_NODES + w0) * LDIM;
        float* o1 = out + ((size_t)b * N_NODES + (v1 ? w1 : w0)) * LDIM;

        #pragma unroll
        for (int nt = 0; nt < 8; ++nt) {
            const int c = nt * 8 + cb;
            const float* a4 = acc + ((nt >> 1) * 8 + (nt & 1) * 4);
            const float2 xv0 = *(const float2*)(x0 + c);
            float2 r0;
            r0.x = a4[0] + fmaf(sc0, xv0.x, bi0);
            r0.y = a4[1] + fmaf(sc0, xv0.y, bi0);
            *(float2*)(o0 + c) = r0;
            if (v1) {
                const float2 xv1 = *(const float2*)(x1 + c);
                float2 r1;
                r1.x = a4[2] + fmaf(sc1, xv1.x, bi1);
                r1.y = a4[3] + fmaf(sc1, xv1.y, bi1);
                *(float2*)(o1 + c) = r1;
            }
        }
    }
}

// ---------------- launcher ---------------------------------------------
extern "C" void kernel_launch(void* const* d_in, const int* in_sizes, int n_in,
                              void* d_out, int out_size) {
    const float* inputs      = (const float*)d_in[0];
    const float* weight_diff = (const float*)d_in[1];
    const float* bias_diff   = (const float*)d_in[2];
    const float* weight_sl   = (const float*)d_in[3];
    const int*   ind         = (const int*)d_in[4];
    const int*   edge_i      = (const int*)d_in[5];
    const int*   edge_j      = (const int*)d_in[6];
    float*       out         = (float*)d_out;

    static bool attr_set = false;   // host-side config only, not a work guard
    if (!attr_set) {
        cudaFuncSetAttribute(gemm_main_kernel,
                             cudaFuncAttributeMaxDynamicSharedMemorySize,
                             MAIN_SMEM);
        attr_set = true;
    }

    build_csr_kernel<<<1, 1024>>>(edge_i, edge_j);
    lap_build_kernel<<<N_SLOTS * MT, 128>>>(weight_diff, weight_sl);
    gemm_main_kernel<<<BATCH, NTHREADS, MAIN_SMEM>>>(inputs, bias_diff, ind, out);
}

// round 15
// speedup vs baseline: 1.6442x; 1.6442x over previous
#include <cuda_runtime.h>
#include <cuda_bf16.h>
#include <cstdint>

#define N_NODES 207
#define N_EDGES 1722
#define LDIM    64
#define BATCH   1024
#define N_SLOTS_PAD 256          // 4 passes * 16 warps * 4 slots
#define ADJ_CAP 5120             // >= 16 * sum_quads(max ng)
#define PACK_N  5128             // +8 u32 pad so prefetch over-read is safe

// ---------------- device-global CSR scratch (no allocs allowed) ------------
__device__ int g_rowptr4[N_SLOTS_PAD + 1];                   // entry start per SORTED SLOT
__device__ unsigned short g_order[N_SLOTS_PAD];              // slot -> node id (0xFFFF invalid)
__device__ __align__(16) unsigned short g_adj_node[ADJ_CAP]; // nbr*128 (byte offset of bf16 row)
__device__ __align__(16) unsigned short g_adj_edge[ADJ_CAP]; // edge idx; N_EDGES = dummy (w=0)

// ---------------- setup: deterministic quad-padded sorted CSR (proven) -----
__global__ __launch_bounds__(1024, 1)
void build_csr_kernel(const int* __restrict__ edge_i,
                      const int* __restrict__ edge_j) {
    __shared__ int s_ei[N_EDGES];
    __shared__ int s_ej[N_EDGES];
    __shared__ int s_ng[N_NODES];
    __shared__ int s_off[N_NODES + 1];
    __shared__ unsigned short s_ord[N_SLOTS_PAD];
    __shared__ int s_wcnt[32][208];
    const int tid  = threadIdx.x;
    const int warp = tid >> 5;
    const int lane = tid & 31;

    for (int i = tid; i < N_EDGES; i += 1024) {
        s_ei[i] = edge_i[i];
        s_ej[i] = edge_j[i];
    }
    for (int v = tid; v < N_NODES + 1; v += 1024) s_off[v] = 0;
    for (int i = tid; i < N_SLOTS_PAD; i += 1024) s_ord[i] = 0xFFFFu;
    for (int t = tid; t < ADJ_CAP; t += 1024) {
        g_adj_node[t] = 0;
        g_adj_edge[t] = (unsigned short)N_EDGES;    // dummy -> weight 0
    }
    for (int i = tid; i < 32 * 208; i += 1024) ((int*)s_wcnt)[i] = 0;
    __syncthreads();

    for (int idx = tid; idx < 2 * N_EDGES; idx += 1024) {
        const int e = idx >> 1;
        atomicAdd(&s_off[(idx & 1) ? s_ej[e] : s_ei[e]], 1);
    }
    __syncthreads();

    if (tid < N_NODES) s_ng[tid] = (s_off[tid] + 3) >> 2;
    __syncthreads();

    // parallel rank sort: desc by ng, tie asc id
    if (tid < N_NODES) {
        const int nv = s_ng[tid];
        int r = 0;
        for (int u = 0; u < N_NODES; ++u) {
            const int nu = s_ng[u];
            r += (nu > nv) || (nu == nv && u < tid);
        }
        s_ord[r] = (unsigned short)tid;
    }
    __syncthreads();

    // quad scan: 64 quads, 2 rounds of 32 (warp 0)
    if (warp == 0) {
        int carryG = 0;
        #pragma unroll
        for (int c = 0; c < 2; ++c) {
            const int q = c * 32 + lane;
            const int a0 = s_ord[4 * q + 0], a1 = s_ord[4 * q + 1];
            const int a2 = s_ord[4 * q + 2], a3 = s_ord[4 * q + 3];
            const int n0 = (a0 != 0xFFFF) ? s_ng[a0] : 0;
            const int n1 = (a1 != 0xFFFF) ? s_ng[a1] : 0;
            const int n2 = (a2 != 0xFFFF) ? s_ng[a2] : 0;
            const int n3 = (a3 != 0xFFFF) ? s_ng[a3] : 0;
            int m = n0 > n1 ? n0 : n1;
            m = m > n2 ? m : n2;
            m = m > n3 ? m : n3;
            int si = m;
            #pragma unroll
            for (int o = 1; o < 32; o <<= 1) {
                const int t = __shfl_up_sync(0xffffffffu, si, o);
                if (lane >= o) si += t;
            }
            const int base = (carryG + si - m) * 16;   // entries
            g_rowptr4[4 * q + 0] = base;
            g_rowptr4[4 * q + 1] = base + 4 * m;
            g_rowptr4[4 * q + 2] = base + 8 * m;
            g_rowptr4[4 * q + 3] = base + 12 * m;
            if (a0 != 0xFFFF) s_off[a0] = base;
            if (a1 != 0xFFFF) s_off[a1] = base + 4 * m;
            if (a2 != 0xFFFF) s_off[a2] = base + 8 * m;
            if (a3 != 0xFFFF) s_off[a3] = base + 12 * m;
            carryG += __shfl_sync(0xffffffffu, si, 31);
        }
        if (lane == 0) g_rowptr4[N_SLOTS_PAD] = carryG * 16;
    }
    __syncthreads();
    for (int i = tid; i < N_SLOTS_PAD; i += 1024) g_order[i] = s_ord[i];

    // single-chunk deterministic scatter: 4 sequential rounds per lane
    int myrank[4], myv[4], mynbr[4], mye[4];
    #pragma unroll
    for (int r = 0; r < 4; ++r) {
        const int idx = tid * 4 + r;
        const bool valid = idx < 2 * N_EDGES;
        int v = 207, nbr = 0, e = 0;
        if (valid) {
            e = idx >> 1;
            if (idx & 1) { v = s_ej[e]; nbr = s_ei[e]; }
            else         { v = s_ei[e]; nbr = s_ej[e]; }
        }
        const int prefix = s_wcnt[warp][v];
        const unsigned mask = __match_any_sync(0xffffffffu, v);
        const int rin = __popc(mask & ((1u << lane) - 1u));
        myv[r] = v; mynbr[r] = nbr; mye[r] = e;
        myrank[r] = prefix + rin;
        __syncwarp();
        if (lane == (__ffs(mask) - 1)) s_wcnt[warp][v] = prefix + __popc(mask);
        __syncwarp();
    }
    __syncthreads();

    if (tid < 208) {
        int run = (tid < N_NODES) ? s_off[tid] : 0;
        #pragma unroll
        for (int w2 = 0; w2 < 32; ++w2) {
            const int t = s_wcnt[w2][tid];
            s_wcnt[w2][tid] = run;
            run += t;
        }
    }
    __syncthreads();

    #pragma unroll
    for (int r = 0; r < 4; ++r) {
        const int idx = tid * 4 + r;
        if (idx < 2 * N_EDGES) {
            const int pos = s_wcnt[warp][myv[r]] + myrank[r];
            g_adj_node[pos] = (unsigned short)(mynbr[r] * 128);  // row byte offset
            g_adj_edge[pos] = (unsigned short)mye[r];
        }
    }
}

// ---------------- main kernel: one CTA (512 thr) per batch, occ 4 ----------
// smem (55.5 KB): bf16 x tile | fp32 slot weights | packed meta | rowp | ord.
// Phase B packs meta from SMEM weights (coalesced global reads only).
// Warp = 4 sorted slots (equal quad-padded ng); lane covers 8 columns.
// Inner loop per 4-entry group: 1 LDS.128 meta (prefetched) +
// 4 x (LDS.128 gather + PRMT + LOP/FADD + 4 HFMA2). Streaming stores for out.
#define S_XU_B    0
#define S_W_B     26496
#define S_PACK_B  33408
#define S_ROWP_B  (33408 + PACK_N * 4)        // 53920
#define S_ORD_B   (S_ROWP_B + 1028)           // 54948
#define SMEM_BYTES (S_ORD_B + 512 + 12)       // 55472

__device__ __forceinline__ __nv_bfloat162 as_bf2(unsigned v) {
    return *reinterpret_cast<__nv_bfloat162*>(&v);
}
__device__ __forceinline__ unsigned as_u32(__nv_bfloat162 v) {
    return *reinterpret_cast<unsigned*>(&v);
}

#define ENTRY(PK) do {                                                \
    const uint4 u = *(const uint4*)(sxb + ((PK) & 0xffffu));          \
    const __nv_bfloat162 wb = as_bf2(__byte_perm((PK), (PK), 0x3232));\
    deg += __uint_as_float((PK) & 0xffff0000u);                       \
    c0 = __hfma2(wb, as_bf2(u.x), c0);                                \
    c1 = __hfma2(wb, as_bf2(u.y), c1);                                \
    c2 = __hfma2(wb, as_bf2(u.z), c2);                                \
    c3 = __hfma2(wb, as_bf2(u.w), c3);                                \
} while (0)

__global__ __launch_bounds__(512, 4)
void diffusion_gcn_kernel(const float*  __restrict__ inputs,      // (B,2,N,L)
                          const float*  __restrict__ weight_diff, // (S,E)
                          const float*  __restrict__ bias_diff,   // (S,N)
                          const float*  __restrict__ weight_sl,   // (S,N)
                          const int*    __restrict__ ind,         // (B,)
                          float*        __restrict__ out)         // (B,N,L)
{
    extern __shared__ char smem[];
    unsigned*       s_xu   = (unsigned*)(smem + S_XU_B);     // bf16 tile, 32 u32/row
    float*          s_w    = (float*)(smem + S_W_B);         // fp32 weights (+wsl reuse)
    unsigned*       s_pack = (unsigned*)(smem + S_PACK_B);   // packed meta
    int*            s_rowp = (int*)(smem + S_ROWP_B);
    unsigned short* s_ord  = (unsigned short*)(smem + S_ORD_B);

    const int b    = blockIdx.x;
    const int tid  = threadIdx.x;
    const int slot = ind[b];
    const float* __restrict__ xg = inputs + (size_t)b * 2 * N_NODES * LDIM;

    // ---- phase A: stage everything (all coalesced) ------------------------
    {   // x -> bf16 tile
        const float4* src = (const float4*)xg;
        uint2* dst = (uint2*)s_xu;
        #pragma unroll 4
        for (int i = tid; i < (N_NODES * LDIM) / 4; i += 512) {
            const float4 v = src[i];
            uint2 p;
            p.x = as_u32(__floats2bfloat162_rn(v.x, v.y));
            p.y = as_u32(__floats2bfloat162_rn(v.z, v.w));
            dst[i] = p;
        }
    }
    {   // slot weight row, zero-padded
        const float* wrow = weight_diff + (size_t)slot * N_EDGES;
        for (int i = tid; i < 1728; i += 512)
            s_w[i] = (i < N_EDGES) ? wrow[i] : 0.0f;
    }
    for (int i = tid; i < N_SLOTS_PAD + 1; i += 512) s_rowp[i] = g_rowptr4[i];
    for (int i = tid; i < N_SLOTS_PAD / 2; i += 512)
        ((unsigned*)s_ord)[i] = ((const unsigned*)g_order)[i];
    __syncthreads();

    // ---- phase B: pack meta from SMEM weights + global CSR (coalesced) ----
    for (int t = tid; t < ADJ_CAP; t += 512) {
        const float w = s_w[(int)g_adj_edge[t]];               // smem gather
        const unsigned wb = (unsigned)__bfloat16_as_ushort(__float2bfloat16(w));
        s_pack[t] = (wb << 16) | (unsigned)g_adj_node[t];      // hi bf16 w | lo byteoff
    }
    if (tid < PACK_N - ADJ_CAP) s_pack[ADJ_CAP + tid] = 0;     // prefetch pad
    __syncthreads();

    // ---- phase C: gather ---------------------------------------------------
    const int warp    = tid >> 5;        // 0..15
    const int lane    = tid & 31;
    const int quarter = lane >> 3;       // slot within quad
    const int hl      = lane & 7;        // 8-column group within slot
    const char* sxb   = (const char*)s_xu + 16 * hl;
    const float* __restrict__ wslrow = weight_sl + (size_t)slot * N_NODES;
    const float* __restrict__ birow  = bias_diff + (size_t)slot * N_NODES;

    #pragma unroll 1
    for (int pass = 0; pass < 4; ++pass) {
        const int sl  = pass * 64 + warp * 4 + quarter;
        const int w   = (int)s_ord[sl];
        const int beg = s_rowp[sl];
        const int ng  = (s_rowp[sl + 1] - beg) >> 2;   // uniform across quad

        const uint4* mp = (const uint4*)(s_pack + beg);
        uint4 p = mp[0];                                // group 0 prefetched

        // prefetch diagonal fp32 row chunk (global, L2-hot)
        const float* xr = (w != 0xFFFF) ? (xg + w * LDIM + 8 * hl) : xg;
        const float4 x0 = *(const float4*)xr;

        __nv_bfloat162 c0 = as_bf2(0u), c1 = as_bf2(0u);
        __nv_bfloat162 c2 = as_bf2(0u), c3 = as_bf2(0u);
        float deg = 0.f;

        #pragma unroll 1
        for (int g = 0; g < ng; ++g) {
            const uint4 pn = mp[g + 1];                 // padded over-read safe
            ENTRY(p.x);
            ENTRY(p.y);
            ENTRY(p.z);
            ENTRY(p.w);
            p = pn;
        }

        if (w != 0xFFFF) {
            const float4 x1 = *(const float4*)(xr + 4);
            const float sc = deg + 1.0f + __ldg(wslrow + w);
            const float bi = __ldg(birow + w);
            const unsigned r0 = as_u32(c0), r1 = as_u32(c1);
            const unsigned r2 = as_u32(c2), r3 = as_u32(c3);
            float4 o0, o1;
            o0.x = fmaf(sc, x0.x, bi - __uint_as_float(r0 << 16));
            o0.y = fmaf(sc, x0.y, bi - __uint_as_float(r0 & 0xffff0000u));
            o0.z = fmaf(sc, x0.z, bi - __uint_as_float(r1 << 16));
            o0.w = fmaf(sc, x0.w, bi - __uint_as_float(r1 & 0xffff0000u));
            o1.x = fmaf(sc, x1.x, bi - __uint_as_float(r2 << 16));
            o1.y = fmaf(sc, x1.y, bi - __uint_as_float(r2 & 0xffff0000u));
            o1.z = fmaf(sc, x1.z, bi - __uint_as_float(r3 << 16));
            o1.w = fmaf(sc, x1.w, bi - __uint_as_float(r3 & 0xffff0000u));
            float* op = out + ((size_t)b * N_NODES + w) * LDIM + 8 * hl;
            __stcs((float4*)op, o0);                    // streaming store
            __stcs((float4*)(op + 4), o1);
        }
    }
}

// ---------------- launcher ---------------------------------------------
extern "C" void kernel_launch(void* const* d_in, const int* in_sizes, int n_in,
                              void* d_out, int out_size) {
    const float* inputs      = (const float*)d_in[0];
    const float* weight_diff = (const float*)d_in[1];
    const float* bias_diff   = (const float*)d_in[2];
    const float* weight_sl   = (const float*)d_in[3];
    const int*   ind         = (const int*)d_in[4];
    const int*   edge_i      = (const int*)d_in[5];
    const int*   edge_j      = (const int*)d_in[6];
    float*       out         = (float*)d_out;

    static bool attr_set = false;   // host-side config only, not a work guard
    if (!attr_set) {
        cudaFuncSetAttribute(diffusion_gcn_kernel,
                             cudaFuncAttributeMaxDynamicSharedMemorySize,
                             SMEM_BYTES);
        attr_set = true;
    }

    build_csr_kernel<<<1, 1024>>>(edge_i, edge_j);
    diffusion_gcn_kernel<<<BATCH, 512, SMEM_BYTES>>>(
        inputs, weight_diff, bias_diff, weight_sl, ind, out);
}